// round 3
// baseline (speedup 1.0000x reference)
#include <cuda_runtime.h>
#include <cuda_fp8.h>
#include <cstdint>
#include <cstddef>

#define DI __device__ __forceinline__

// ---------------- problem constants ----------------
static constexpr int MT = 8192;   // tokens
static constexpr int NT = 4096;   // out features
static constexpr int KT = 4096;   // in features
static constexpr float FP8MAX = 448.0f;
static constexpr float AMAX_EPS = 1e-8f;
static constexpr float MOMENTUM = 0.95f;

// ---------------- GEMM tiling ----------------
static constexpr int BM = 128;
static constexpr int BN = 128;
static constexpr int BK = 128;                 // bytes of e4m3 along K per stage
static constexpr int NSTAGES = 4;
static constexpr int K_ITERS = KT / BK;        // 32
static constexpr int A_BYTES = BM * BK;        // 16384
static constexpr int B_BYTES = BN * BK;        // 16384
static constexpr int STAGE_BYTES = A_BYTES + B_BYTES;          // 32768
static constexpr int DYN_SMEM = NSTAGES * STAGE_BYTES;         // 131072
static constexpr int THREADS = 256;            // 8 warps: 2 (m) x 4 (n), warp tile 64x32

// ---------------- scratch (static device arrays: allocation-guard safe) ----------------
__device__ __align__(128) uint8_t g_Xq[(size_t)MT * KT];
__device__ __align__(128) uint8_t g_Wq[(size_t)NT * KT];
__device__ unsigned g_amax_bits[2];

// ---------------- PTX helpers (base sm_103 target ONLY — no tcgen05/TMA) ----------------
DI uint32_t smem_u32(const void* p) {
    uint32_t a;
    asm("{ .reg .u64 t; cvta.to.shared.u64 t, %1; cvt.u32.u64 %0, t; }" : "=r"(a) : "l"(p));
    return a;
}
DI void cp_async16(uint32_t s, const void* g) {
    asm volatile("cp.async.cg.shared.global [%0], [%1], 16;" :: "r"(s), "l"(g) : "memory");
}
DI void cp_commit() { asm volatile("cp.async.commit_group;" ::: "memory"); }
template <int N> DI void cp_wait() {
    asm volatile("cp.async.wait_group %0;" :: "n"(N) : "memory");
}
DI void ldsm_x4(uint32_t& r0, uint32_t& r1, uint32_t& r2, uint32_t& r3, uint32_t addr) {
    asm volatile("ldmatrix.sync.aligned.m8n8.x4.shared.b16 {%0,%1,%2,%3}, [%4];"
                 : "=r"(r0), "=r"(r1), "=r"(r2), "=r"(r3) : "r"(addr));
}
DI void mma_e4m3(float& c0, float& c1, float& c2, float& c3,
                 uint32_t a0, uint32_t a1, uint32_t a2, uint32_t a3,
                 uint32_t b0, uint32_t b1) {
    asm volatile(
        "mma.sync.aligned.m16n8k32.row.col.f32.e4m3.e4m3.f32 "
        "{%0,%1,%2,%3}, {%4,%5,%6,%7}, {%8,%9}, {%0,%1,%2,%3};"
        : "+f"(c0), "+f"(c1), "+f"(c2), "+f"(c3)
        : "r"(a0), "r"(a1), "r"(a2), "r"(a3), "r"(b0), "r"(b1));
}

// ---------------- kernel 1: quantize + absmax ----------------
__global__ void quant_amax_kernel(const float* __restrict__ x, uint8_t* __restrict__ q,
                                  int n4, const float* __restrict__ amax_in,
                                  unsigned* __restrict__ amax_slot) {
    __shared__ float smax[8];
    const float s = FP8MAX / fmaxf(amax_in[0], AMAX_EPS);
    float lmax = 0.0f;
    const float4* x4 = (const float4*)x;
    uint32_t* q4 = (uint32_t*)q;
    for (int i = blockIdx.x * blockDim.x + threadIdx.x; i < n4; i += gridDim.x * blockDim.x) {
        float4 v = x4[i];
        lmax = fmaxf(lmax, fmaxf(fmaxf(fabsf(v.x), fabsf(v.y)), fmaxf(fabsf(v.z), fabsf(v.w))));
        uint32_t p =
            (uint32_t)__nv_cvt_float_to_fp8(v.x * s, __NV_SATFINITE, __NV_E4M3)
          | ((uint32_t)__nv_cvt_float_to_fp8(v.y * s, __NV_SATFINITE, __NV_E4M3) << 8)
          | ((uint32_t)__nv_cvt_float_to_fp8(v.z * s, __NV_SATFINITE, __NV_E4M3) << 16)
          | ((uint32_t)__nv_cvt_float_to_fp8(v.w * s, __NV_SATFINITE, __NV_E4M3) << 24);
        q4[i] = p;
    }
    #pragma unroll
    for (int o = 16; o > 0; o >>= 1) lmax = fmaxf(lmax, __shfl_xor_sync(0xffffffffu, lmax, o));
    if ((threadIdx.x & 31) == 0) smax[threadIdx.x >> 5] = lmax;
    __syncthreads();
    if (threadIdx.x == 0) {
        float b = smax[0];
        for (int w = 1; w < (int)(blockDim.x >> 5); ++w) b = fmaxf(b, smax[w]);
        atomicMax(amax_slot, __float_as_uint(b));
    }
}

// ---------------- kernel 2: fp8 mma.sync GEMM + bias epilogue ----------------
__global__ void __launch_bounds__(THREADS, 1) fp8_gemm_kernel(
    const float* __restrict__ bias,
    const float* __restrict__ in_amax,
    const float* __restrict__ w_amax,
    float* __restrict__ out)
{
    extern __shared__ uint8_t dynsmem[];
    __shared__ float bias_s[BN];

    const int tid  = threadIdx.x;
    const int wid  = tid >> 5;
    const int lane = tid & 31;
    const int wm   = wid >> 2;        // 0..1  (m position, 64 rows each)
    const int wn   = wid & 3;         // 0..3  (n position, 32 cols each)

    const int n_tiles = NT / BN;                       // 32
    const int m0 = (int)(blockIdx.x >> 5) * BM;        // n-fast rasterization
    const int n0 = (int)(blockIdx.x & (n_tiles - 1)) * BN;

    const uint32_t smem = smem_u32(dynsmem);

    const uint8_t* Ag = g_Xq + (size_t)m0 * KT;
    const uint8_t* Bg = g_Wq + (size_t)n0 * KT;

    // per-thread cp.async chunk coords (8 chunks of 16B per thread per stage)
    // chunks 0..1023 -> A (128 rows x 8 chunks), 1024..2047 -> B
    // swizzle: swz(o) = o ^ ((o>>3)&0x70) with 128B rows
    for (int i = tid; i < BN; i += THREADS) bias_s[i] = bias[n0 + i];

    // ---- prologue: stages 0..NSTAGES-2 ----
    #pragma unroll
    for (int s = 0; s < NSTAGES - 1; ++s) {
        const uint32_t a_s = smem + s * STAGE_BYTES;
        const uint32_t b_s = a_s + A_BYTES;
        const int kb = s * BK;
        #pragma unroll
        for (int i = 0; i < 8; ++i) {
            const int q = tid + i * THREADS;
            if (q < 1024) {
                const int row = q >> 3, ch = (q & 7) << 4;
                const uint32_t o = (uint32_t)(row * BK + ch);
                cp_async16(a_s + (o ^ ((o >> 3) & 0x70)), Ag + (size_t)row * KT + kb + ch);
            } else {
                const int qb = q - 1024;
                const int row = qb >> 3, ch = (qb & 7) << 4;
                const uint32_t o = (uint32_t)(row * BK + ch);
                cp_async16(b_s + (o ^ ((o >> 3) & 0x70)), Bg + (size_t)row * KT + kb + ch);
            }
        }
        cp_commit();
    }

    // ---- per-lane ldmatrix offsets (unswizzled row base + xor mask) ----
    // A x4: row = wm*64 + am*16 + (lane&15), kbyte = (lane>>4)*16 + katom*32
    const int a_row_l = (lane & 15);
    const uint32_t a_kchunk = (uint32_t)((lane >> 4) << 4);
    // B x4: row = wn*32 + pair*16 + (lane>>4)*8 + (lane&7), kbyte = ((lane>>3)&1)*16 + katom*32
    const int b_row_l = ((lane >> 4) << 3) + (lane & 7);
    const uint32_t b_kchunk = (uint32_t)(((lane >> 3) & 1) << 4);

    uint32_t a_base[4], b_base[2];
    uint32_t a_xor, b_xor;
    {
        #pragma unroll
        for (int am = 0; am < 4; ++am) {
            const int r = wm * 64 + am * 16 + a_row_l;
            a_base[am] = (uint32_t)(r * BK);
        }
        a_xor = (uint32_t)(((wm * 64 + a_row_l) & 7) << 4);
        #pragma unroll
        for (int bp = 0; bp < 2; ++bp) {
            const int r = wn * 32 + bp * 16 + b_row_l;
            b_base[bp] = (uint32_t)(r * BK);
        }
        b_xor = (uint32_t)(((wn * 32 + b_row_l) & 7) << 4);
    }

    float acc[4][4][4];
    #pragma unroll
    for (int i = 0; i < 4; ++i)
        #pragma unroll
        for (int j = 0; j < 4; ++j)
            #pragma unroll
            for (int k = 0; k < 4; ++k) acc[i][j][k] = 0.0f;

    // ---- main loop ----
    for (int it = 0; it < K_ITERS; ++it) {
        cp_wait<NSTAGES - 2>();
        __syncthreads();

        // issue copies for stage it+NSTAGES-1
        const int nit = it + NSTAGES - 1;
        if (nit < K_ITERS) {
            const int st = nit & (NSTAGES - 1);
            const uint32_t a_s = smem + st * STAGE_BYTES;
            const uint32_t b_s = a_s + A_BYTES;
            const int kb = nit * BK;
            #pragma unroll
            for (int i = 0; i < 8; ++i) {
                const int q = tid + i * THREADS;
                if (q < 1024) {
                    const int row = q >> 3, ch = (q & 7) << 4;
                    const uint32_t o = (uint32_t)(row * BK + ch);
                    cp_async16(a_s + (o ^ ((o >> 3) & 0x70)), Ag + (size_t)row * KT + kb + ch);
                } else {
                    const int qb = q - 1024;
                    const int row = qb >> 3, ch = (qb & 7) << 4;
                    const uint32_t o = (uint32_t)(row * BK + ch);
                    cp_async16(b_s + (o ^ ((o >> 3) & 0x70)), Bg + (size_t)row * KT + kb + ch);
                }
            }
        }
        cp_commit();

        // compute on stage it
        const uint32_t a_s = smem + (it & (NSTAGES - 1)) * STAGE_BYTES;
        const uint32_t b_s = a_s + A_BYTES;

        #pragma unroll
        for (int ka = 0; ka < BK / 32; ++ka) {
            const uint32_t koffA = ((uint32_t)(ka * 32) + a_kchunk) ^ a_xor;
            const uint32_t koffB = ((uint32_t)(ka * 32) + b_kchunk) ^ b_xor;
            uint32_t af[4][4];
            #pragma unroll
            for (int am = 0; am < 4; ++am)
                ldsm_x4(af[am][0], af[am][1], af[am][2], af[am][3],
                        a_s + a_base[am] + koffA);
            uint32_t bf[2][4];
            #pragma unroll
            for (int bp = 0; bp < 2; ++bp)
                ldsm_x4(bf[bp][0], bf[bp][1], bf[bp][2], bf[bp][3],
                        b_s + b_base[bp] + koffB);
            #pragma unroll
            for (int am = 0; am < 4; ++am) {
                #pragma unroll
                for (int an = 0; an < 4; ++an) {
                    const int bp = an >> 1;
                    const int hl = (an & 1) << 1;  // 0 -> regs{0,1}, 1 -> regs{2,3}
                    mma_e4m3(acc[am][an][0], acc[am][an][1], acc[am][an][2], acc[am][an][3],
                             af[am][0], af[am][1], af[am][2], af[am][3],
                             bf[bp][hl + 0], bf[bp][hl + 1]);
                }
            }
        }
    }

    // ---- epilogue: scale + bias + store ----
    const float sx = FP8MAX / fmaxf(in_amax[0], AMAX_EPS);
    const float sw = FP8MAX / fmaxf(w_amax[0], AMAX_EPS);
    const float inv = 1.0f / (sx * sw);

    const int row_base = m0 + wm * 64 + (lane >> 2);
    const int col_base = n0 + wn * 32 + (lane & 3) * 2;
    #pragma unroll
    for (int am = 0; am < 4; ++am) {
        #pragma unroll
        for (int an = 0; an < 4; ++an) {
            const int c = col_base + an * 8;
            const float b0 = bias_s[c - n0], b1 = bias_s[c - n0 + 1];
            const int r0 = row_base + am * 16;
            float2 v0 = make_float2(fmaf(acc[am][an][0], inv, b0),
                                    fmaf(acc[am][an][1], inv, b1));
            float2 v1 = make_float2(fmaf(acc[am][an][2], inv, b0),
                                    fmaf(acc[am][an][3], inv, b1));
            *(float2*)(out + (size_t)r0 * NT + c) = v0;
            *(float2*)(out + (size_t)(r0 + 8) * NT + c) = v1;
        }
    }
}

// ---------------- kernel 3: amax EMA finalize ----------------
__global__ void finalize_amax_kernel(const float* __restrict__ in_amax,
                                     const float* __restrict__ w_amax,
                                     const unsigned* __restrict__ bits,
                                     float* __restrict__ out, int out_size) {
    const float xm = __uint_as_float(bits[0]);
    const float wm = __uint_as_float(bits[1]);
    out[out_size - 2] = fmaxf(fmaxf(in_amax[0] * MOMENTUM, xm), AMAX_EPS);
    out[out_size - 1] = fmaxf(fmaxf(w_amax[0] * MOMENTUM, wm), AMAX_EPS);
}

// ---------------- launch ----------------
extern "C" void kernel_launch(void* const* d_in, const int* in_sizes, int n_in,
                              void* d_out, int out_size) {
    (void)in_sizes; (void)n_in;
    const float* x       = (const float*)d_in[0];
    const float* w       = (const float*)d_in[1];
    const float* bias    = (const float*)d_in[2];
    const float* in_amax = (const float*)d_in[3];
    const float* w_amax  = (const float*)d_in[4];
    float* out = (float*)d_out;

    void* p;
    cudaGetSymbolAddress(&p, g_Xq);        uint8_t* xq = (uint8_t*)p;
    cudaGetSymbolAddress(&p, g_Wq);        uint8_t* wq = (uint8_t*)p;
    cudaGetSymbolAddress(&p, g_amax_bits); unsigned* bits = (unsigned*)p;

    cudaMemsetAsync(bits, 0, 2 * sizeof(unsigned));
    quant_amax_kernel<<<1024, 256>>>(x, xq, MT * KT / 4, in_amax, bits + 0);
    quant_amax_kernel<<<512, 256>>>(w, wq, NT * KT / 4, w_amax, bits + 1);

    cudaFuncSetAttribute(fp8_gemm_kernel,
                         cudaFuncAttributeMaxDynamicSharedMemorySize, DYN_SMEM);
    fp8_gemm_kernel<<<(MT / BM) * (NT / BN), THREADS, DYN_SMEM>>>(bias, in_amax, w_amax, out);

    finalize_amax_kernel<<<1, 1>>>(in_amax, w_amax, bits, out, out_size);
}

// round 5
// speedup vs baseline: 1.0394x; 1.0394x over previous
#include <cuda_runtime.h>
#include <cuda_fp8.h>
#include <cstdint>
#include <cstddef>

#define DI __device__ __forceinline__

// ---------------- problem constants ----------------
static constexpr int MT = 8192;   // tokens
static constexpr int NT = 4096;   // out features
static constexpr int KT = 4096;   // in features
static constexpr float FP8MAX = 448.0f;
static constexpr float AMAX_EPS = 1e-8f;
static constexpr float MOMENTUM = 0.95f;

// ---------------- GEMM tiling ----------------
static constexpr int BM = 128;
static constexpr int BN = 128;
static constexpr int BK = 128;                 // bytes of e4m3 along K per stage
static constexpr int NSTAGES = 3;
static constexpr int K_ITERS = KT / BK;        // 32
static constexpr int A_BYTES = BM * BK;        // 16384
static constexpr int B_BYTES = BN * BK;        // 16384
static constexpr int STAGE_BYTES = A_BYTES + B_BYTES;          // 32768
static constexpr int DYN_SMEM = NSTAGES * STAGE_BYTES;         // 98304 -> 2 CTAs/SM
static constexpr int THREADS = 256;            // 8 warps: 2 (m) x 4 (n), warp tile 64x32

static constexpr int QX_BLOCKS = 1024;
static constexpr int QW_BLOCKS = 512;

// ---------------- scratch (static device arrays: allocation-guard safe) ----------------
__device__ __align__(128) uint8_t g_Xq[(size_t)MT * KT];
__device__ __align__(128) uint8_t g_Wq[(size_t)NT * KT];
__device__ float g_partX[QX_BLOCKS];
__device__ float g_partW[QW_BLOCKS];

// ---------------- PTX helpers (base sm_103 target ONLY — no tcgen05/TMA) ----------------
DI uint32_t smem_u32(const void* p) {
    uint32_t a;
    asm("{ .reg .u64 t; cvta.to.shared.u64 t, %1; cvt.u32.u64 %0, t; }" : "=r"(a) : "l"(p));
    return a;
}
DI void cp_async16(uint32_t s, const void* g) {
    asm volatile("cp.async.cg.shared.global [%0], [%1], 16;" :: "r"(s), "l"(g) : "memory");
}
DI void cp_commit() { asm volatile("cp.async.commit_group;" ::: "memory"); }
template <int N> DI void cp_wait() {
    asm volatile("cp.async.wait_group %0;" :: "n"(N) : "memory");
}
DI void ldsm_x4(uint32_t& r0, uint32_t& r1, uint32_t& r2, uint32_t& r3, uint32_t addr) {
    asm volatile("ldmatrix.sync.aligned.m8n8.x4.shared.b16 {%0,%1,%2,%3}, [%4];"
                 : "=r"(r0), "=r"(r1), "=r"(r2), "=r"(r3) : "r"(addr));
}
DI void mma_e4m3(float& c0, float& c1, float& c2, float& c3,
                 uint32_t a0, uint32_t a1, uint32_t a2, uint32_t a3,
                 uint32_t b0, uint32_t b1) {
    asm volatile(
        "mma.sync.aligned.m16n8k32.row.col.f32.e4m3.e4m3.f32 "
        "{%0,%1,%2,%3}, {%4,%5,%6,%7}, {%8,%9}, {%0,%1,%2,%3};"
        : "+f"(c0), "+f"(c1), "+f"(c2), "+f"(c3)
        : "r"(a0), "r"(a1), "r"(a2), "r"(a3), "r"(b0), "r"(b1));
}

// ---------------- kernel 1: quantize + per-block absmax (no atomics, no memset) ----------------
__global__ void quant_amax_kernel(const float* __restrict__ x, uint8_t* __restrict__ q,
                                  int n4, const float* __restrict__ amax_in,
                                  float* __restrict__ part) {
    __shared__ float smax[8];
    const float s = FP8MAX / fmaxf(amax_in[0], AMAX_EPS);
    float lmax = 0.0f;
    const float4* x4 = (const float4*)x;
    uint32_t* q4 = (uint32_t*)q;
    for (int i = blockIdx.x * blockDim.x + threadIdx.x; i < n4; i += gridDim.x * blockDim.x) {
        float4 v = x4[i];
        lmax = fmaxf(lmax, fmaxf(fmaxf(fabsf(v.x), fabsf(v.y)), fmaxf(fabsf(v.z), fabsf(v.w))));
        uint32_t p =
            (uint32_t)__nv_cvt_float_to_fp8(v.x * s, __NV_SATFINITE, __NV_E4M3)
          | ((uint32_t)__nv_cvt_float_to_fp8(v.y * s, __NV_SATFINITE, __NV_E4M3) << 8)
          | ((uint32_t)__nv_cvt_float_to_fp8(v.z * s, __NV_SATFINITE, __NV_E4M3) << 16)
          | ((uint32_t)__nv_cvt_float_to_fp8(v.w * s, __NV_SATFINITE, __NV_E4M3) << 24);
        q4[i] = p;
    }
    #pragma unroll
    for (int o = 16; o > 0; o >>= 1) lmax = fmaxf(lmax, __shfl_xor_sync(0xffffffffu, lmax, o));
    if ((threadIdx.x & 31) == 0) smax[threadIdx.x >> 5] = lmax;
    __syncthreads();
    if (threadIdx.x == 0) {
        float b = smax[0];
        for (int w = 1; w < (int)(blockDim.x >> 5); ++w) b = fmaxf(b, smax[w]);
        part[blockIdx.x] = b;
    }
}

// ---------------- kernel 2: fp8 mma.sync GEMM + bias epilogue + fused amax finalize ----------------
__global__ void __launch_bounds__(THREADS, 2) fp8_gemm_kernel(
    const float* __restrict__ bias,
    const float* __restrict__ in_amax,
    const float* __restrict__ w_amax,
    const float* __restrict__ partX,
    const float* __restrict__ partW,
    float* __restrict__ out, int out_size)
{
    extern __shared__ uint8_t dynsmem[];
    __shared__ float bias_s[BN];

    const int tid  = threadIdx.x;
    const int wid  = tid >> 5;
    const int lane = tid & 31;
    const int wm   = wid >> 2;        // 0..1  (m position, 64 rows each)
    const int wn   = wid & 3;         // 0..3  (n position, 32 cols each)

    const int n_tiles = NT / BN;                       // 32
    const int m0 = (int)(blockIdx.x >> 5) * BM;        // n-fast rasterization
    const int n0 = (int)(blockIdx.x & (n_tiles - 1)) * BN;

    const uint32_t smem = smem_u32(dynsmem);

    const uint8_t* Ag = g_Xq + (size_t)m0 * KT;
    const uint8_t* Bg = g_Wq + (size_t)n0 * KT;

    for (int i = tid; i < BN; i += THREADS) bias_s[i] = bias[n0 + i];

    // ---- prologue: stages 0..NSTAGES-2 ----
    #pragma unroll
    for (int s = 0; s < NSTAGES - 1; ++s) {
        const uint32_t a_s = smem + s * STAGE_BYTES;
        const uint32_t b_s = a_s + A_BYTES;
        const int kb = s * BK;
        #pragma unroll
        for (int i = 0; i < 8; ++i) {
            const int q = tid + i * THREADS;
            if (q < 1024) {
                const int row = q >> 3, ch = (q & 7) << 4;
                const uint32_t o = (uint32_t)(row * BK + ch);
                cp_async16(a_s + (o ^ ((o >> 3) & 0x70)), Ag + (size_t)row * KT + kb + ch);
            } else {
                const int qb = q - 1024;
                const int row = qb >> 3, ch = (qb & 7) << 4;
                const uint32_t o = (uint32_t)(row * BK + ch);
                cp_async16(b_s + (o ^ ((o >> 3) & 0x70)), Bg + (size_t)row * KT + kb + ch);
            }
        }
        cp_commit();
    }

    // ---- per-lane ldmatrix offsets ----
    const int a_row_l = (lane & 15);
    const uint32_t a_kchunk = (uint32_t)((lane >> 4) << 4);
    const int b_row_l = ((lane >> 4) << 3) + (lane & 7);
    const uint32_t b_kchunk = (uint32_t)(((lane >> 3) & 1) << 4);

    uint32_t a_base[4], b_base[2];
    uint32_t a_xor, b_xor;
    {
        #pragma unroll
        for (int am = 0; am < 4; ++am) {
            const int r = wm * 64 + am * 16 + a_row_l;
            a_base[am] = (uint32_t)(r * BK);
        }
        a_xor = (uint32_t)(((wm * 64 + a_row_l) & 7) << 4);
        #pragma unroll
        for (int bp = 0; bp < 2; ++bp) {
            const int r = wn * 32 + bp * 16 + b_row_l;
            b_base[bp] = (uint32_t)(r * BK);
        }
        b_xor = (uint32_t)(((wn * 32 + b_row_l) & 7) << 4);
    }

    float acc[4][4][4];
    #pragma unroll
    for (int i = 0; i < 4; ++i)
        #pragma unroll
        for (int j = 0; j < 4; ++j)
            #pragma unroll
            for (int k = 0; k < 4; ++k) acc[i][j][k] = 0.0f;

    // ---- main loop ----
    for (int it = 0; it < K_ITERS; ++it) {
        cp_wait<NSTAGES - 2>();
        __syncthreads();

        const int nit = it + NSTAGES - 1;
        if (nit < K_ITERS) {
            const int st = nit % NSTAGES;
            const uint32_t a_s = smem + st * STAGE_BYTES;
            const uint32_t b_s = a_s + A_BYTES;
            const int kb = nit * BK;
            #pragma unroll
            for (int i = 0; i < 8; ++i) {
                const int q = tid + i * THREADS;
                if (q < 1024) {
                    const int row = q >> 3, ch = (q & 7) << 4;
                    const uint32_t o = (uint32_t)(row * BK + ch);
                    cp_async16(a_s + (o ^ ((o >> 3) & 0x70)), Ag + (size_t)row * KT + kb + ch);
                } else {
                    const int qb = q - 1024;
                    const int row = qb >> 3, ch = (qb & 7) << 4;
                    const uint32_t o = (uint32_t)(row * BK + ch);
                    cp_async16(b_s + (o ^ ((o >> 3) & 0x70)), Bg + (size_t)row * KT + kb + ch);
                }
            }
        }
        cp_commit();

        // compute on stage it
        const uint32_t a_s = smem + (it % NSTAGES) * STAGE_BYTES;
        const uint32_t b_s = a_s + A_BYTES;

        #pragma unroll
        for (int ka = 0; ka < BK / 32; ++ka) {
            const uint32_t koffA = ((uint32_t)(ka * 32) + a_kchunk) ^ a_xor;
            const uint32_t koffB = ((uint32_t)(ka * 32) + b_kchunk) ^ b_xor;
            uint32_t af[4][4];
            #pragma unroll
            for (int am = 0; am < 4; ++am)
                ldsm_x4(af[am][0], af[am][1], af[am][2], af[am][3],
                        a_s + a_base[am] + koffA);
            uint32_t bf[2][4];
            #pragma unroll
            for (int bp = 0; bp < 2; ++bp)
                ldsm_x4(bf[bp][0], bf[bp][1], bf[bp][2], bf[bp][3],
                        b_s + b_base[bp] + koffB);
            #pragma unroll
            for (int am = 0; am < 4; ++am) {
                #pragma unroll
                for (int an = 0; an < 4; ++an) {
                    const int bp = an >> 1;
                    const int hl = (an & 1) << 1;
                    mma_e4m3(acc[am][an][0], acc[am][an][1], acc[am][an][2], acc[am][an][3],
                             af[am][0], af[am][1], af[am][2], af[am][3],
                             bf[bp][hl + 0], bf[bp][hl + 1]);
                }
            }
        }
    }

    // ---- epilogue: scale + bias + store ----
    const float sx = FP8MAX / fmaxf(in_amax[0], AMAX_EPS);
    const float sw = FP8MAX / fmaxf(w_amax[0], AMAX_EPS);
    const float inv = 1.0f / (sx * sw);

    const int row_base = m0 + wm * 64 + (lane >> 2);
    const int col_base = n0 + wn * 32 + (lane & 3) * 2;
    #pragma unroll
    for (int am = 0; am < 4; ++am) {
        #pragma unroll
        for (int an = 0; an < 4; ++an) {
            const int c = col_base + an * 8;
            const float b0 = bias_s[c - n0], b1 = bias_s[c - n0 + 1];
            const int r0 = row_base + am * 16;
            float2 v0 = make_float2(fmaf(acc[am][an][0], inv, b0),
                                    fmaf(acc[am][an][1], inv, b1));
            float2 v1 = make_float2(fmaf(acc[am][an][2], inv, b0),
                                    fmaf(acc[am][an][3], inv, b1));
            *(float2*)(out + (size_t)r0 * NT + c) = v0;
            *(float2*)(out + (size_t)(r0 + 8) * NT + c) = v1;
        }
    }

    // ---- fused amax EMA finalize (block 0, warp 0) ----
    if (blockIdx.x == 0 && wid == 0) {
        float mx = 0.0f, mw = 0.0f;
        for (int i = lane; i < QX_BLOCKS; i += 32) mx = fmaxf(mx, partX[i]);
        for (int i = lane; i < QW_BLOCKS; i += 32) mw = fmaxf(mw, partW[i]);
        #pragma unroll
        for (int o = 16; o > 0; o >>= 1) {
            mx = fmaxf(mx, __shfl_xor_sync(0xffffffffu, mx, o));
            mw = fmaxf(mw, __shfl_xor_sync(0xffffffffu, mw, o));
        }
        if (lane == 0) {
            out[out_size - 2] = fmaxf(fmaxf(in_amax[0] * MOMENTUM, mx), AMAX_EPS);
            out[out_size - 1] = fmaxf(fmaxf(w_amax[0] * MOMENTUM, mw), AMAX_EPS);
        }
    }
}

// ---------------- launch (exactly 3 kernel launches per call) ----------------
extern "C" void kernel_launch(void* const* d_in, const int* in_sizes, int n_in,
                              void* d_out, int out_size) {
    (void)in_sizes; (void)n_in;
    const float* x       = (const float*)d_in[0];
    const float* w       = (const float*)d_in[1];
    const float* bias    = (const float*)d_in[2];
    const float* in_amax = (const float*)d_in[3];
    const float* w_amax  = (const float*)d_in[4];
    float* out = (float*)d_out;

    void* p;
    cudaGetSymbolAddress(&p, g_Xq);    uint8_t* xq = (uint8_t*)p;
    cudaGetSymbolAddress(&p, g_Wq);    uint8_t* wq = (uint8_t*)p;
    cudaGetSymbolAddress(&p, g_partX); float* partX = (float*)p;
    cudaGetSymbolAddress(&p, g_partW); float* partW = (float*)p;

    quant_amax_kernel<<<QX_BLOCKS, 256>>>(x, xq, MT * KT / 4, in_amax, partX);
    quant_amax_kernel<<<QW_BLOCKS, 256>>>(w, wq, NT * KT / 4, w_amax, partW);

    cudaFuncSetAttribute(fp8_gemm_kernel,
                         cudaFuncAttributeMaxDynamicSharedMemorySize, DYN_SMEM);
    fp8_gemm_kernel<<<(MT / BM) * (NT / BN), THREADS, DYN_SMEM>>>(
        bias, in_amax, w_amax, partX, partW, out, out_size);
}